// round 13
// baseline (speedup 1.0000x reference)
#include <cuda_runtime.h>

// x[64, 64, 64, 128] fp32.
//   out1 = FWHT along axis 1 (i), element stride 8192
//   out2 = FWHT along axis 2 (j) of out1, element stride 128
// d_out = [out1 | out2].
//
// Lag pipeline (out1 re-read served from L2; ~344 MB DRAM traffic), with the
// phases REORDERED inside each block: consume first, produce second.
//   group g (32 blocks): [pass 2 of batch g-LAG]  then  [pass 1 of batch g].
// Effects vs round 10 (produce-then-consume):
//   - the dependency a block waits on is LAG groups old -> spin ~ 0, and the
//     wait is at block START (block has issued nothing yet; other resident
//     blocks cover the SM).
//   - the __threadfence (store-drain) + signal move to block END, after the
//     last memory phase -> the drain no longer separates two phases of the
//     same block; it overlaps with block exit / other blocks.
// Counters self-reset for graph replay: the last pass-2 block of a batch
// clears both counters (all waiters have already passed the spin).

#define THREADS 256
#define NB 64
#define BPB 32                       // blocks per batch-pass
#define LAG 3
#define GRID ((NB + LAG) * BPB)      // 2144

__device__ int g_cnt1[NB];           // pass-1 completions per batch
__device__ int g_cnt2[NB];           // pass-2 completions per batch

__device__ __forceinline__ void butterfly64(float v[64])
{
#pragma unroll
    for (int h = 1; h < 64; h <<= 1)
#pragma unroll
        for (int s = 0; s < 64; s += 2 * h)
#pragma unroll
            for (int k = 0; k < h; k++) {
                float a = v[s + k], b = v[s + k + h];
                v[s + k]     = a + b;
                v[s + k + h] = a - b;
            }
}

__global__ __launch_bounds__(THREADS)
void wht2_lag(const float* __restrict__ x,
              float* __restrict__ out1,
              float* __restrict__ out2)
{
    const int grp = blockIdx.x / BPB;            // 0 .. NB+LAG-1
    const int sub = blockIdx.x % BPB;
    const unsigned col = (unsigned)sub * THREADS + threadIdx.x;   // 0..8191

    float v[64];

    // ---------------- phase 1: CONSUME — out2[m] = FWHT_j(out1[m]) ----------------
    if (grp >= LAG) {
        const int m = grp - LAG;

        if (threadIdx.x == 0) {
            while (*(volatile int*)&g_cnt1[m] < BPB)
                __nanosleep(32);
        }
        __syncthreads();
        __threadfence();                              // acquire

        const size_t mbase = (size_t)m * (64u * 8192u);
        const size_t base  = mbase + (size_t)(col >> 7) * 8192u + (col & 127u);
        const float* pi = out1 + base;
#pragma unroll
        for (int k = 0; k < 64; k++)
            v[k] = __ldcs(pi + (size_t)k * 128);      // L2-hot; evict after use

        butterfly64(v);

        float* po = out2 + base;
#pragma unroll
        for (int k = 0; k < 64; k++)
            __stcs(po + (size_t)k * 128, v[k]);       // use-once write

        // self-reset (safe: all waiters on g_cnt1[m] already passed the spin)
        __syncthreads();
        if (threadIdx.x == 0) {
            int done = atomicAdd(&g_cnt2[m], 1) + 1;
            if (done == BPB) {
                atomicExch(&g_cnt2[m], 0);
                atomicExch(&g_cnt1[m], 0);
            }
        }
    }

    // ---------------- phase 2: PRODUCE — out1[grp] = FWHT_i(x[grp]) ----------------
    if (grp < NB) {
        const size_t bbase = (size_t)grp * (64u * 8192u);
        const float* px = x + bbase + col;            // col = (j,c)
#pragma unroll
        for (int k = 0; k < 64; k++)
            v[k] = __ldcs(px + (size_t)k * 8192);     // use-once read of x

        butterfly64(v);

        float* po = out1 + bbase + col;
#pragma unroll
        for (int k = 0; k < 64; k++)
            po[(size_t)k * 8192] = v[k];              // keep in L2 for pass 2

        __threadfence();                               // release — at block END
        __syncthreads();
        if (threadIdx.x == 0)
            atomicAdd(&g_cnt1[grp], 1);
    }
}

extern "C" void kernel_launch(void* const* d_in, const int* in_sizes, int n_in,
                              void* d_out, int out_size)
{
    const float* x = (const float*)d_in[0];
    float* out1 = (float*)d_out;
    float* out2 = out1 + (size_t)64 * 64 * 64 * 128;

    wht2_lag<<<GRID, THREADS>>>(x, out1, out2);
}

// round 14
// speedup vs baseline: 3.5058x; 3.5058x over previous
#include <cuda_runtime.h>

// x[64, 64, 64, 128] fp32.
//   out1 = FWHT along axis 1 (i), element stride 8192
//   out2 = FWHT along axis 2 (j) of out1, element stride 128
// d_out = [out1 | out2].
//
// Produce-then-consume lag pipeline (round-10 structure) with LAG raised
// above the residency-wave span (~444 blocks = ~14 groups):
//   group g (32 blocks): [pass 1 of batch g] then [pass 2 of batch g-16].
// With LAG=16 the consumed batch was produced in the PREVIOUS wave, so the
// spin is ~0 and pass-1/pass-2 memory phases interleave across resident
// blocks in steady state (LAG=3 kept the dependency inside the wave, which
// degenerated into alternating all-produce / all-consume phases stalling at
// every boundary -> DRAM only 60% busy).
// L2 hot footprint ~ (LAG + wave) * 2 MB ~= 60 MB < 126 MB, so out1 re-reads
// stay L2 hits; out1 reaches DRAM only via writeback. ~384 MB total traffic.
// Counters self-reset (last pass-2 block of a batch clears both) so state is
// zero at every graph replay; single kernel launch.

#define THREADS 256
#define NB 64
#define BPB 32                       // blocks per batch-pass
#define LAG 16
#define GRID ((NB + LAG) * BPB)      // 2560

__device__ int g_cnt1[NB];           // pass-1 completions per batch
__device__ int g_cnt2[NB];           // pass-2 completions per batch

__device__ __forceinline__ void butterfly64(float v[64])
{
#pragma unroll
    for (int h = 1; h < 64; h <<= 1)
#pragma unroll
        for (int s = 0; s < 64; s += 2 * h)
#pragma unroll
            for (int k = 0; k < h; k++) {
                float a = v[s + k], b = v[s + k + h];
                v[s + k]     = a + b;
                v[s + k + h] = a - b;
            }
}

__global__ __launch_bounds__(THREADS)
void wht2_lag(const float* __restrict__ x,
              float* __restrict__ out1,
              float* __restrict__ out2)
{
    const int grp = blockIdx.x / BPB;            // 0 .. NB+LAG-1
    const int sub = blockIdx.x % BPB;
    const unsigned col = (unsigned)sub * THREADS + threadIdx.x;   // 0..8191

    float v[64];

    // ---------------- pass 1: out1[grp] = FWHT_i(x[grp]) ----------------
    if (grp < NB) {
        const size_t bbase = (size_t)grp * (64u * 8192u);
        const float* px = x + bbase + col;           // col = (j,c)
#pragma unroll
        for (int k = 0; k < 64; k++)
            v[k] = __ldcs(px + (size_t)k * 8192);    // use-once read of x

        butterfly64(v);

        float* po = out1 + bbase + col;
#pragma unroll
        for (int k = 0; k < 64; k++)
            po[(size_t)k * 8192] = v[k];             // keep in L2 for pass 2

        __threadfence();                              // release out1 stores
        __syncthreads();
        if (threadIdx.x == 0)
            atomicAdd(&g_cnt1[grp], 1);
    }

    // ---------------- pass 2: out2[m] = FWHT_j(out1[m]), m = grp-LAG ----------------
    if (grp >= LAG) {
        const int m = grp - LAG;

        if (threadIdx.x == 0) {
            while (*(volatile int*)&g_cnt1[m] < BPB)   // produced a wave ago -> ~no spin
                __nanosleep(32);
        }
        __syncthreads();
        __threadfence();                               // acquire

        const size_t mbase = (size_t)m * (64u * 8192u);
        const size_t base  = mbase + (size_t)(col >> 7) * 8192u + (col & 127u);
        const float* pi = out1 + base;
#pragma unroll
        for (int k = 0; k < 64; k++)
            v[k] = __ldcs(pi + (size_t)k * 128);      // L2-hot; evict after use

        butterfly64(v);

        float* po = out2 + base;
#pragma unroll
        for (int k = 0; k < 64; k++)
            __stcs(po + (size_t)k * 128, v[k]);       // use-once write

        // self-reset: last finishing pass-2 block clears both counters
        // (all waiters on g_cnt1[m] have already passed the spin).
        __syncthreads();
        if (threadIdx.x == 0) {
            int done = atomicAdd(&g_cnt2[m], 1) + 1;
            if (done == BPB) {
                atomicExch(&g_cnt2[m], 0);
                atomicExch(&g_cnt1[m], 0);
            }
        }
    }
}

extern "C" void kernel_launch(void* const* d_in, const int* in_sizes, int n_in,
                              void* d_out, int out_size)
{
    const float* x = (const float*)d_in[0];
    float* out1 = (float*)d_out;
    float* out2 = out1 + (size_t)64 * 64 * 64 * 128;

    wht2_lag<<<GRID, THREADS>>>(x, out1, out2);
}